// round 14
// baseline (speedup 1.0000x reference)
#include <cuda_runtime.h>
#include <cuda_bf16.h>
#include <mma.h>
#include <cstdint>

using namespace nvcuda;

// ---------------- problem constants ----------------
#define BB      8
#define CDIM    128
#define HH      112
#define WWID    112
#define LTOK    (HH*WWID)        // 12544
#define MTOK    (BB*LTOK)        // 100352
#define WS      7
#define NTOK    (WS*WS)          // 49
#define NWIN    2048
#define HEADS   4
#define HD      32
#define SHIFT   3
#define MLP     512

// ---------------- scratch (device globals) ----------------
__device__ float          g_xt[(size_t)MTOK*CDIM];     // token-major shortcut (fp32)
__device__ __nv_bfloat16  g_qkv[(size_t)MTOK*3*CDIM];  // QKV bf16, window order
__device__ __nv_bfloat16  g_attnout[(size_t)MTOK*CDIM];// attention out, window order
__device__ float          g_y[(size_t)MTOK*CDIM];      // residual1, token order
__device__ __nv_bfloat16  g_h[(size_t)MTOK*CDIM];      // LN2 out, token order
__device__ __nv_bfloat16  g_hh[(size_t)MTOK*MLP];      // gelu(fc1)

__device__ __nv_bfloat16  g_wqkv[CDIM*3*CDIM];         // [K][N]
__device__ __nv_bfloat16  g_wproj[CDIM*CDIM];          // [K][N]
__device__ __nv_bfloat16  g_wfc1[CDIM*MLP];            // [K][N]
__device__ __nv_bfloat16  g_wfc2[MLP*CDIM];            // [K][N]
__device__ float          g_bias[HEADS*NTOK*NTOK];

// ---------------- helpers ----------------
__device__ __forceinline__ uint32_t smem_u32(const void* p) {
    uint32_t a;
    asm("{ .reg .u64 t; cvta.to.shared.u64 t, %1; cvt.u32.u64 %0, t; }" : "=r"(a) : "l"(p));
    return a;
}
__device__ __forceinline__ void cpa16(uint32_t s, const void* g) {
    asm volatile("cp.async.cg.shared.global [%0], [%1], 16;" :: "r"(s), "l"(g) : "memory");
}
__device__ __forceinline__ void cpa_commit() {
    asm volatile("cp.async.commit_group;" ::: "memory");
}
__device__ __forceinline__ float warp_sum(float v) {
#pragma unroll
    for (int o = 16; o; o >>= 1) v += __shfl_xor_sync(0xffffffffu, v, o);
    return v;
}
__device__ __forceinline__ float warp_max(float v) {
#pragma unroll
    for (int o = 16; o; o >>= 1) v = fmaxf(v, __shfl_xor_sync(0xffffffffu, v, o));
    return v;
}
__device__ __forceinline__ int winrow_to_token(int i) {
    int win = i / NTOK, n = i - win * NTOK;
    int b   = win >> 8;
    int wr  = win & 255;
    int wi  = wr >> 4, wj = wr & 15;
    int r   = n / WS,  c = n - r * WS;
    int hs  = wi * WS + r + SHIFT; if (hs >= HH)   hs  -= HH;
    int ws_ = wj * WS + c + SHIFT; if (ws_ >= WWID) ws_ -= WWID;
    return b * LTOK + hs * WWID + ws_;
}
__device__ __forceinline__ uint32_t pack2(float a, float b) {
    __nv_bfloat162 t = __floats2bfloat162_rn(a, b);
    return *reinterpret_cast<uint32_t*>(&t);
}
__device__ __forceinline__ void store_bf16x4(__nv_bfloat16* p, float a, float b, float c, float d) {
    uint2 u; u.x = pack2(a, b); u.y = pack2(c, d);
    *reinterpret_cast<uint2*>(p) = u;
}

// ---------------- setup ----------------
#define W0 (CDIM*3*CDIM)
#define W1 (CDIM*CDIM)
#define W2 (CDIM*MLP)
#define W3 (MLP*CDIM)
#define WTOT (W0+W1+W2+W3)
#define SETUP_TOT (WTOT + HEADS*NTOK*NTOK)

__global__ void k_setup(const float* __restrict__ qkv_w, const float* __restrict__ proj_w,
                        const float* __restrict__ fc1_w, const float* __restrict__ fc2_w,
                        const float* __restrict__ tbl, const int* __restrict__ relidx) {
    int i = blockIdx.x * blockDim.x + threadIdx.x;
    if (i >= SETUP_TOT) return;
    if (i < W0)           { g_wqkv[i]          = __float2bfloat16(qkv_w[i]);          return; }
    if (i < W0+W1)        { g_wproj[i-W0]      = __float2bfloat16(proj_w[i-W0]);      return; }
    if (i < W0+W1+W2)     { g_wfc1[i-W0-W1]    = __float2bfloat16(fc1_w[i-W0-W1]);    return; }
    if (i < WTOT)         { g_wfc2[i-W0-W1-W2] = __float2bfloat16(fc2_w[i-W0-W1-W2]); return; }
    int j = i - WTOT;
    int h = j / (NTOK*NTOK);
    int e = j - h * (NTOK*NTOK);
    g_bias[h*NTOK*NTOK + e] = tbl[relidx[e]*HEADS + h];
}

// ---------------- transpose (B,C,L) -> token-major g_xt ----------------
__global__ __launch_bounds__(256) void k_transp(const float* __restrict__ x) {
    __shared__ float t[CDIM*33];
    int b  = blockIdx.y;
    int l0 = blockIdx.x * 32;
    int tid = threadIdx.x;
    int lane = tid & 31, warp = tid >> 5;

    const float* xb = x + (size_t)b * CDIM * LTOK + l0;
    {
        int l = tid & 31, cg = tid >> 5;
#pragma unroll
        for (int it = 0; it < 16; it++) {
            int c = it * 8 + cg;
            t[c * 33 + l] = xb[(size_t)c * LTOK + l];
        }
    }
    __syncthreads();
#pragma unroll
    for (int kk = 0; kk < 4; kk++) {
        int tt = warp * 4 + kk;
        int l  = l0 + tt;
        float4 v;
        v.x = t[(lane*4+0)*33 + tt];
        v.y = t[(lane*4+1)*33 + tt];
        v.z = t[(lane*4+2)*33 + tt];
        v.w = t[(lane*4+3)*33 + tt];
        reinterpret_cast<float4*>(g_xt + (size_t)(b * LTOK + l) * CDIM)[lane] = v;
    }
}

// ---------------- WMMA attention (R11-measured 82.9us, frozen) ----------------
__global__ __launch_bounds__(128, 8) void k_attn() {
    __shared__ __nv_bfloat16 sQ[64*40];   // Q, then V (O-phase)
    __shared__ __nv_bfloat16 sK[64*40];   // K, then patch scratch (O-phase)
    __shared__ float         sS[64*68];   // S fp32 -> P bf16 (in-place)

    int bid  = blockIdx.x;
    int win  = bid >> 2;
    int head = bid & 3;
    int tid  = threadIdx.x;
    int warp = tid >> 5, lane = tid & 31;

    const uint32_t sQ32 = smem_u32(sQ), sK32 = smem_u32(sK);
    const __nv_bfloat16* src = g_qkv + (size_t)win * NTOK * (3*CDIM) + head * HD;

#pragma unroll
    for (int it = 0; it < 4; it++) {
        int idx = it * 128 + tid;
        if (idx < 392) {
            int q = idx >> 2, part = idx & 3;
            int n = q >> 1, m = q & 1;
            cpa16((m ? sK32 : sQ32) + (uint32_t)(n*80 + part*16),
                  src + (size_t)n*(3*CDIM) + m*CDIM + part*8);
        }
    }
    cpa_commit();
    asm volatile("cp.async.wait_group 0;" ::: "memory");
    __syncthreads();

    {
        int wrow = warp * 16;
        wmma::fragment<wmma::accumulator,16,16,16,float> s[4];
#pragma unroll
        for (int j = 0; j < 4; j++) wmma::fill_fragment(s[j], 0.f);
#pragma unroll
        for (int i = 0; i < 2; i++) {
            wmma::fragment<wmma::matrix_a,16,16,16,__nv_bfloat16,wmma::row_major> qa;
            wmma::load_matrix_sync(qa, &sQ[wrow*40 + 16*i], 40);
#pragma unroll
            for (int j = 0; j < 4; j++) {
                wmma::fragment<wmma::matrix_b,16,16,16,__nv_bfloat16,wmma::col_major> kb;
                wmma::load_matrix_sync(kb, &sK[(16*j)*40 + 16*i], 40);
                wmma::mma_sync(s[j], qa, kb, s[j]);
            }
        }
#pragma unroll
        for (int j = 0; j < 4; j++)
            wmma::store_matrix_sync(&sS[wrow*68 + 16*j], s[j], 68, wmma::mem_row_major);
    }
    __syncthreads();

#pragma unroll
    for (int it = 0; it < 2; it++) {
        int idx = it * 128 + tid;
        if (idx < 196) {
            int n = idx >> 2, part = idx & 3;
            cpa16(sQ32 + (uint32_t)(n*80 + part*16),
                  src + (size_t)n*(3*CDIM) + 2*CDIM + part*8);
        }
    }
    cpa_commit();
    for (int i = tid; i < 300; i += 128) {
        int r = i / 20, c = i - r * 20;
        reinterpret_cast<uint32_t*>(sQ + (49 + r)*40)[c] = 0u;
    }

    {
        __nv_bfloat16* sP = reinterpret_cast<__nv_bfloat16*>(sS);
        const float scale = 0.17677669529663687f;
        for (int r = warp; r < NTOK; r += 4) {
            const float* brow = &g_bias[head*NTOK*NTOK + r*NTOK];
            int c2 = lane + 32;
            float v1 = sS[r*68 + lane] * scale + __ldg(&brow[lane]);
            float v2 = (c2 < NTOK) ? sS[r*68 + c2] * scale + __ldg(&brow[c2]) : -1e30f;
            float mx = warp_max(fmaxf(v1, v2));
            float e1 = __expf(v1 - mx);
            float e2 = (c2 < NTOK) ? __expf(v2 - mx) : 0.f;
            float rinv = 1.f / warp_sum(e1 + e2);
            sP[r*136 + lane] = __float2bfloat16(e1 * rinv);
            sP[r*136 + c2]   = __float2bfloat16(e2 * rinv);
        }
    }
    asm volatile("cp.async.wait_group 0;" ::: "memory");
    __syncthreads();

    {
        const __nv_bfloat16* sP = reinterpret_cast<const __nv_bfloat16*>(sS);
        const __nv_bfloat16* sV = sQ;
        int wrow = warp * 16;
        wmma::fragment<wmma::accumulator,16,16,16,float> o[2];
#pragma unroll
        for (int j = 0; j < 2; j++) wmma::fill_fragment(o[j], 0.f);
#pragma unroll
        for (int i = 0; i < 4; i++) {
            wmma::fragment<wmma::matrix_a,16,16,16,__nv_bfloat16,wmma::row_major> pa;
            wmma::load_matrix_sync(pa, &sP[wrow*136 + 16*i], 136);
#pragma unroll
            for (int j = 0; j < 2; j++) {
                wmma::fragment<wmma::matrix_b,16,16,16,__nv_bfloat16,wmma::row_major> vb;
                wmma::load_matrix_sync(vb, &sV[(16*i)*40 + 16*j], 40);
                wmma::mma_sync(o[j], pa, vb, o[j]);
            }
        }
        float* patch = reinterpret_cast<float*>(sK) + warp * 320;
        int r2 = lane >> 1;
        int cc = (lane & 1) * 8;
        int n  = wrow + r2;
#pragma unroll
        for (int j = 0; j < 2; j++) {
            wmma::store_matrix_sync(patch, o[j], 20, wmma::mem_row_major);
            __syncwarp();
            float4 v0 = *reinterpret_cast<float4*>(patch + r2*20 + cc);
            float4 v1 = *reinterpret_cast<float4*>(patch + r2*20 + cc + 4);
            __syncwarp();
            if (n < NTOK) {
                uint4 u;
                u.x = pack2(v0.x, v0.y); u.y = pack2(v0.z, v0.w);
                u.z = pack2(v1.x, v1.y); u.w = pack2(v1.z, v1.w);
                *reinterpret_cast<uint4*>(g_attnout + ((size_t)win * NTOK + n) * CDIM
                                          + head * HD + j*16 + cc) = u;
            }
        }
    }
}

// ---------------- qkv/fc1: 64-row M tiles (fc2-measured shape), 2 CTA/SM -----------
// EPI: 0 = QKV (LN1-fused A-load), 2 = FC1 (cp.async A, gelu)
#define TILEB   34816   // 128 x 136 bf16
#define TILEA64 17408   // 64 x 136 bf16
#define PATCHB  10240   // 8 warps x 320 floats

extern __shared__ __align__(16) unsigned char gdyn[];

template<int NT128, int EPI>
__device__ __forceinline__ void gemm64_body(
    const __nv_bfloat16* __restrict__ A,       // unused for EPI==0
    const __nv_bfloat16* __restrict__ Bw,      // [K=128][N]
    const float* __restrict__ bias,
    const float* __restrict__ ln_g,
    const float* __restrict__ ln_b)
{
    const int N = NT128 * 128, K = 128;
    unsigned char* sAb = gdyn;                     // 17408
    unsigned char* sBb = gdyn + TILEA64;           // 2 x 34816
    const uint32_t sA32 = smem_u32(sAb), sB32 = smem_u32(sBb);

    const int tid = threadIdx.x;
    const int warp = tid >> 5, lane = tid & 31;
    const int bm = blockIdx.x * 64;
    const int wm = (warp & 1) * 32, wn = (warp >> 1) * 32;   // 2x4 warp grid
    const int G = NT128;

    auto issue = [&](int g) {
        const __nv_bfloat16* src = Bw + g*128;
        uint32_t sb = sB32 + (uint32_t)(g & 1) * TILEB;
#pragma unroll
        for (int it = 0; it < 8; it++) {
            int idx = it * 256 + tid;
            int r = idx >> 4, c = idx & 15;
            cpa16(sb + r*272 + c*16, src + (size_t)r * N + c*8);
        }
        if (EPI == 2 && g == 0) {
            const __nv_bfloat16* sa = A + (size_t)bm * K;
#pragma unroll
            for (int it = 0; it < 4; it++) {
                int idx = it * 256 + tid;
                int r = idx >> 4, c = idx & 15;
                cpa16(sA32 + r*272 + c*16, sa + (size_t)r * K + c*8);
            }
        }
        cpa_commit();
    };

    issue(0);
    if (G > 1) issue(1);

    if (EPI == 0) {
        // LN1-fused A staging: gather 64 window-order rows from g_xt
        __nv_bfloat16* sA = reinterpret_cast<__nv_bfloat16*>(sAb);
        float4 gg = reinterpret_cast<const float4*>(ln_g)[lane];
        float4 bb = reinterpret_cast<const float4*>(ln_b)[lane];
#pragma unroll
        for (int r = warp; r < 64; r += 8) {
            int token = winrow_to_token(bm + r);
            float4 v = reinterpret_cast<const float4*>(g_xt + (size_t)token * CDIM)[lane];
            float s  = v.x + v.y + v.z + v.w;
            float s2 = v.x*v.x + v.y*v.y + v.z*v.z + v.w*v.w;
            s  = warp_sum(s); s2 = warp_sum(s2);
            float mean = s * (1.f / CDIM);
            float var  = s2 * (1.f / CDIM) - mean * mean;
            float inv  = rsqrtf(var + 1e-5f);
            store_bf16x4(sA + r*136 + lane*4,
                         (v.x - mean) * inv * gg.x + bb.x,
                         (v.y - mean) * inv * gg.y + bb.y,
                         (v.z - mean) * inv * gg.z + bb.z,
                         (v.w - mean) * inv * gg.w + bb.w);
        }
    }

    wmma::fragment<wmma::accumulator,16,16,16,float> acc[2][2];

#pragma unroll 1
    for (int g = 0; g < G; g++) {
        if (g + 1 < G) asm volatile("cp.async.wait_group 1;" ::: "memory");
        else           asm volatile("cp.async.wait_group 0;" ::: "memory");
        __syncthreads();

#pragma unroll
        for (int i = 0; i < 2; i++)
#pragma unroll
            for (int j = 0; j < 2; j++) wmma::fill_fragment(acc[i][j], 0.f);

        const __nv_bfloat16* pA = reinterpret_cast<const __nv_bfloat16*>(sAb);
        const __nv_bfloat16* pB = reinterpret_cast<const __nv_bfloat16*>(
            sBb + (size_t)(g & 1) * TILEB);
#pragma unroll
        for (int kk = 0; kk < 8; kk++) {
            wmma::fragment<wmma::matrix_a,16,16,16,__nv_bfloat16,wmma::row_major> af[2];
#pragma unroll
            for (int i = 0; i < 2; i++)
                wmma::load_matrix_sync(af[i], &pA[(wm + 16*i)*136 + kk*16], 136);
#pragma unroll
            for (int j = 0; j < 2; j++) {
                wmma::fragment<wmma::matrix_b,16,16,16,__nv_bfloat16,wmma::row_major> bf;
                wmma::load_matrix_sync(bf, &pB[(kk*16)*136 + wn + 16*j], 136);
#pragma unroll
                for (int i = 0; i < 2; i++)
                    wmma::mma_sync(acc[i][j], af[i], bf, acc[i][j]);
            }
        }
        __syncthreads();              // B buffer (g&1) consumed
        if (g + 2 < G) issue(g + 2);  // prefetch overlaps epilogue

        // dedicated-patch epilogue (no block syncs)
        const int ncol = (EPI == 0) ? 3*CDIM : MLP;
        __nv_bfloat16* base = (EPI == 0) ? g_qkv : g_hh;
        float* patch = reinterpret_cast<float*>(gdyn + TILEA64 + 2*TILEB) + warp * 320;
        int r2 = lane >> 1;
        int cc = (lane & 1) * 8;
#pragma unroll
        for (int i = 0; i < 2; i++) {
#pragma unroll
            for (int j = 0; j < 2; j++) {
                wmma::store_matrix_sync(patch, acc[i][j], 20, wmma::mem_row_major);
                __syncwarp();
                float4 v0 = *reinterpret_cast<float4*>(patch + r2*20 + cc);
                float4 v1 = *reinterpret_cast<float4*>(patch + r2*20 + cc + 4);
                __syncwarp();
                int gr = bm + wm + 16*i + r2;
                int gc = g*128 + wn + 16*j + cc;
                float4 b0 = __ldg(reinterpret_cast<const float4*>(bias + gc));
                float4 b1 = __ldg(reinterpret_cast<const float4*>(bias + gc + 4));
                v0.x += b0.x; v0.y += b0.y; v0.z += b0.z; v0.w += b0.w;
                v1.x += b1.x; v1.y += b1.y; v1.z += b1.z; v1.w += b1.w;
                if (EPI == 2) {
                    const float is2 = 0.70710678118654752f;
                    v0.x = 0.5f*v0.x*(1.f+erff(v0.x*is2));
                    v0.y = 0.5f*v0.y*(1.f+erff(v0.y*is2));
                    v0.z = 0.5f*v0.z*(1.f+erff(v0.z*is2));
                    v0.w = 0.5f*v0.w*(1.f+erff(v0.w*is2));
                    v1.x = 0.5f*v1.x*(1.f+erff(v1.x*is2));
                    v1.y = 0.5f*v1.y*(1.f+erff(v1.y*is2));
                    v1.z = 0.5f*v1.z*(1.f+erff(v1.z*is2));
                    v1.w = 0.5f*v1.w*(1.f+erff(v1.w*is2));
                }
                uint4 o;
                o.x = pack2(v0.x, v0.y); o.y = pack2(v0.z, v0.w);
                o.z = pack2(v1.x, v1.y); o.w = pack2(v1.z, v1.w);
                *reinterpret_cast<uint4*>(base + (size_t)gr * ncol + gc) = o;
            }
        }
    }
}

__global__ __launch_bounds__(256) void k_gemm_qkv(const float* bias, const float* g1, const float* b1) {
    gemm64_body<3,0>(nullptr, g_wqkv, bias, g1, b1);
}
__global__ __launch_bounds__(256) void k_gemm_fc1(const float* bias) {
    gemm64_body<4,2>(g_h, g_wfc1, bias, nullptr, nullptr);
}

// ---------------- proj: 16x128 warp tiles, reg/patch LN2 epilogue (R13, frozen) ----
__global__ __launch_bounds__(256) void k_gemm_proj(const float* __restrict__ bias,
                                                   const float* __restrict__ ln_g,
                                                   const float* __restrict__ ln_b) {
    unsigned char* sAb = gdyn;
    unsigned char* sBb = gdyn + TILEB;
    const uint32_t sA32 = smem_u32(sAb), sB32 = smem_u32(sBb);

    const int tid = threadIdx.x;
    const int warp = tid >> 5, lane = tid & 31;
    const int bm = blockIdx.x * 128;
    const int wm = warp * 16;

    {
        const __nv_bfloat16* sa = g_attnout + (size_t)bm * CDIM;
#pragma unroll
        for (int it = 0; it < 8; it++) {
            int idx = it * 256 + tid;
            int r = idx >> 4, c = idx & 15;
            cpa16(sA32 + r*272 + c*16, sa + (size_t)r * CDIM + c*8);
        }
#pragma unroll
        for (int it = 0; it < 8; it++) {
            int idx = it * 256 + tid;
            int r = idx >> 4, c = idx & 15;
            cpa16(sB32 + r*272 + c*16, g_wproj + (size_t)r * CDIM + c*8);
        }
        cpa_commit();
    }
    asm volatile("cp.async.wait_group 0;" ::: "memory");
    __syncthreads();

    wmma::fragment<wmma::accumulator,16,16,16,float> acc[8];
#pragma unroll
    for (int j = 0; j < 8; j++) wmma::fill_fragment(acc[j], 0.f);
    {
        const __nv_bfloat16* pA = reinterpret_cast<const __nv_bfloat16*>(sAb);
        const __nv_bfloat16* pB = reinterpret_cast<const __nv_bfloat16*>(sBb);
#pragma unroll
        for (int kk = 0; kk < 8; kk++) {
            wmma::fragment<wmma::matrix_a,16,16,16,__nv_bfloat16,wmma::row_major> af;
            wmma::load_matrix_sync(af, &pA[wm*136 + kk*16], 136);
#pragma unroll
            for (int j = 0; j < 8; j++) {
                wmma::fragment<wmma::matrix_b,16,16,16,__nv_bfloat16,wmma::row_major> bf;
                wmma::load_matrix_sync(bf, &pB[(kk*16)*136 + 16*j], 136);
                wmma::mma_sync(acc[j], af, bf, acc[j]);
            }
        }
    }
    __syncthreads();

    float* patch = reinterpret_cast<float*>(gdyn) + warp * 2112;
#pragma unroll
    for (int j = 0; j < 8; j++)
        wmma::store_matrix_sync(&patch[16*j], acc[j], 132, wmma::mem_row_major);
    __syncwarp();

    float4 pb = reinterpret_cast<const float4*>(bias)[lane];
    float4 gg = reinterpret_cast<const float4*>(ln_g)[lane];
    float4 lb = reinterpret_cast<const float4*>(ln_b)[lane];
#pragma unroll
    for (int r = 0; r < 16; r++) {
        int token = winrow_to_token(bm + wm + r);
        float4 v = *reinterpret_cast<float4*>(&patch[r*132 + lane*4]);
        float4 x = reinterpret_cast<const float4*>(g_xt + (size_t)token*CDIM)[lane];
        float4 y;
        y.x = v.x + pb.x + x.x;  y.y = v.y + pb.y + x.y;
        y.z = v.z + pb.z + x.z;  y.w = v.w + pb.w + x.w;
        reinterpret_cast<float4*>(g_y + (size_t)token*CDIM)[lane] = y;
        float s  = y.x + y.y + y.z + y.w;
        float s2 = y.x*y.x + y.y*y.y + y.z*y.z + y.w*y.w;
        s = warp_sum(s); s2 = warp_sum(s2);
        float mean = s * (1.f / CDIM);
        float var  = s2 * (1.f / CDIM) - mean * mean;
        float inv  = rsqrtf(var + 1e-5f);
        store_bf16x4(g_h + (size_t)token*CDIM + lane*4,
                     (y.x - mean) * inv * gg.x + lb.x,
                     (y.y - mean) * inv * gg.y + lb.y,
                     (y.z - mean) * inv * gg.z + lb.z,
                     (y.w - mean) * inv * gg.w + lb.w);
    }
}

// ---------------- fc2: 64-row M tiles, 2 CTA/SM, K=512 in 4 chunks (R12, frozen) ----
__global__ __launch_bounds__(256) void k_gemm_fc2(const float* __restrict__ bias,
                                                  float* __restrict__ outf) {
    unsigned char* sAb = gdyn;                    // 2 x 17408
    unsigned char* sBb = gdyn + 2*TILEA64;        // 2 x 34816
    const uint32_t sA32 = smem_u32(sAb), sB32 = smem_u32(sBb);

    const int tid = threadIdx.x;
    const int warp = tid >> 5, lane = tid & 31;
    const int bm = blockIdx.x * 64;
    const int wm = (warp & 1) * 32, wn = (warp >> 1) * 32;

    auto issue = [&](int g) {
        {
            const __nv_bfloat16* src = g_wfc2 + (size_t)(g*128) * CDIM;
            uint32_t sb = sB32 + (uint32_t)(g & 1) * TILEB;
#pragma unroll
            for (int it = 0; it < 8; it++) {
                int idx = it * 256 + tid;
                int r = idx >> 4, c = idx & 15;
                cpa16(sb + r*272 + c*16, src + (size_t)r * CDIM + c*8);
            }
        }
        {
            const __nv_bfloat16* src = g_hh + (size_t)bm * MLP + g*128;
            uint32_t sa = sA32 + (uint32_t)(g & 1) * TILEA64;
#pragma unroll
            for (int it = 0; it < 4; it++) {
                int idx = it * 256 + tid;
                int r = idx >> 4, c = idx & 15;
                cpa16(sa + r*272 + c*16, src + (size_t)r * MLP + c*8);
            }
        }
        cpa_commit();
    };

    issue(0);
    issue(1);

    wmma::fragment<wmma::accumulator,16,16,16,float> acc[2][2];
#pragma unroll
    for (int i = 0; i < 2; i++)
#pragma unroll
        for (int j = 0; j < 2; j++) wmma::fill_fragment(acc[i][j], 0.f);

#pragma unroll 1
    for (int g = 0; g < 4; g++) {
        if (g < 3) asm volatile("cp.async.wait_group 1;" ::: "memory");
        else       asm volatile("cp.async.wait_group 0;" ::: "memory");
        __syncthreads();

        const __nv_bfloat16* pA = reinterpret_cast<const __nv_bfloat16*>(
            sAb + (size_t)(g & 1) * TILEA64);
        const __nv_bfloat16* pB = reinterpret_cast<const __nv_bfloat16*>(
            sBb + (size_t)(g & 1) * TILEB);
#pragma unroll
        for (int kk = 0; kk < 8; kk++) {
            wmma::fragment<wmma::matrix_a,16,16,16,__nv_bfloat16,wmma::row_major> af[2];
#pragma unroll
            for (int i = 0; i < 2; i++)
                wmma::load_matrix_sync(af[i], &pA[(wm + 16*i)*136 + kk*16], 136);
#pragma unroll
            for (int j = 0; j < 2; j++) {
                wmma::fragment<wmma::matrix_b,16,16,16,__nv_bfloat16,wmma::row_major> bf;
                wmma::load_matrix_sync(bf, &pB[(kk*16)*136 + wn + 16*j], 136);
#pragma unroll
                for (int i = 0; i < 2; i++)
                    wmma::mma_sync(acc[i][j], af[i], bf, acc[i][j]);
            }
        }
        __syncthreads();
        if (g + 2 < 4) issue(g + 2);
    }

    float* sC = reinterpret_cast<float*>(sBb + TILEB);
#pragma unroll
    for (int i = 0; i < 2; i++)
#pragma unroll
        for (int j = 0; j < 2; j++)
            wmma::store_matrix_sync(&sC[(wm + 16*i)*132 + wn + 16*j],
                                    acc[i][j], 132, wmma::mem_row_major);
    __syncthreads();

    for (int e = tid; e < 64*128; e += 256) {
        int r = e >> 7, c = e & 127;
        sC[r*132 + c] += __ldg(&bias[c]) + g_y[(size_t)(bm + r)*CDIM + c];
    }
    __syncthreads();

    int b  = bm / LTOK;
    int l0 = bm - b * LTOK;
    float* ob = outf + (size_t)b * CDIM * LTOK + l0;
    int l = tid & 63, cb = tid >> 6;
#pragma unroll
    for (int it = 0; it < 32; it++) {
        int c = it * 4 + cb;
        ob[(size_t)c * LTOK + l] = sC[l*132 + c];
    }
}

// ---------------- launch ----------------
extern "C" void kernel_launch(void* const* d_in, const int* in_sizes, int n_in,
                              void* d_out, int out_size) {
    const float* x      = (const float*)d_in[0];
    const float* n1g    = (const float*)d_in[1];
    const float* n1b    = (const float*)d_in[2];
    const float* qkv_w  = (const float*)d_in[3];
    const float* qkv_b  = (const float*)d_in[4];
    const float* tbl    = (const float*)d_in[5];
    const int*   relidx = (const int*)d_in[6];
    const float* proj_w = (const float*)d_in[7];
    const float* proj_b = (const float*)d_in[8];
    const float* n2g    = (const float*)d_in[9];
    const float* n2b    = (const float*)d_in[10];
    const float* fc1_w  = (const float*)d_in[11];
    const float* fc1_b  = (const float*)d_in[12];
    const float* fc2_w  = (const float*)d_in[13];
    const float* fc2_b  = (const float*)d_in[14];
    float* out = (float*)d_out;

    const int GSM_QF  = TILEA64 + 2*TILEB + PATCHB; //  97280: qkv/fc1 (A64 + 2B + patch)
    const int GSM_PRJ = 2 * TILEB;                  //  69632: proj
    const int GSM_FC2 = 2 * TILEA64 + 2 * TILEB;    // 104448: fc2

    cudaFuncSetAttribute(k_gemm_qkv,  cudaFuncAttributeMaxDynamicSharedMemorySize, GSM_QF);
    cudaFuncSetAttribute(k_gemm_fc1,  cudaFuncAttributeMaxDynamicSharedMemorySize, GSM_QF);
    cudaFuncSetAttribute(k_gemm_proj, cudaFuncAttributeMaxDynamicSharedMemorySize, GSM_PRJ);
    cudaFuncSetAttribute(k_gemm_fc2,  cudaFuncAttributeMaxDynamicSharedMemorySize, GSM_FC2);

    k_setup<<<(SETUP_TOT + 255)/256, 256>>>(qkv_w, proj_w, fc1_w, fc2_w, tbl, relidx);
    k_transp<<<dim3(LTOK/32, BB), 256>>>(x);
    k_gemm_qkv<<<MTOK/64, 256, GSM_QF>>>(qkv_b, n1g, n1b);
    k_attn<<<NWIN*HEADS, 128>>>();
    k_gemm_proj<<<MTOK/128, 256, GSM_PRJ>>>(proj_b, n2g, n2b);
    k_gemm_fc1<<<MTOK/64, 256, GSM_QF>>>(fc1_b);
    k_gemm_fc2<<<MTOK/64, 256, GSM_FC2>>>(fc2_b, out);
}

// round 15
// speedup vs baseline: 1.0234x; 1.0234x over previous
#include <cuda_runtime.h>
#include <cuda_bf16.h>
#include <mma.h>
#include <cstdint>

using namespace nvcuda;

// ---------------- problem constants ----------------
#define BB      8
#define CDIM    128
#define HH      112
#define WWID    112
#define LTOK    (HH*WWID)        // 12544
#define MTOK    (BB*LTOK)        // 100352
#define WS      7
#define NTOK    (WS*WS)          // 49
#define NWIN    2048
#define HEADS   4
#define HD      32
#define SHIFT   3
#define MLP     512

// ---------------- scratch (device globals) ----------------
__device__ float          g_xt[(size_t)MTOK*CDIM];     // token-major shortcut (fp32)
__device__ __nv_bfloat16  g_qkv[(size_t)MTOK*3*CDIM];  // QKV bf16, window order
__device__ __nv_bfloat16  g_attnout[(size_t)MTOK*CDIM];// attention out, window order
__device__ float          g_y[(size_t)MTOK*CDIM];      // residual1, token order
__device__ __nv_bfloat16  g_h[(size_t)MTOK*CDIM];      // LN2 out, token order
__device__ __nv_bfloat16  g_hh[(size_t)MTOK*MLP];      // gelu(fc1)

__device__ __nv_bfloat16  g_wqkv[CDIM*3*CDIM];         // [K][N]
__device__ __nv_bfloat16  g_wproj[CDIM*CDIM];          // [K][N]
__device__ __nv_bfloat16  g_wfc1[CDIM*MLP];            // [K][N]
__device__ __nv_bfloat16  g_wfc2[MLP*CDIM];            // [K][N]
__device__ float          g_bias[HEADS*NTOK*NTOK];

// ---------------- helpers ----------------
__device__ __forceinline__ uint32_t smem_u32(const void* p) {
    uint32_t a;
    asm("{ .reg .u64 t; cvta.to.shared.u64 t, %1; cvt.u32.u64 %0, t; }" : "=r"(a) : "l"(p));
    return a;
}
__device__ __forceinline__ void cpa16(uint32_t s, const void* g) {
    asm volatile("cp.async.cg.shared.global [%0], [%1], 16;" :: "r"(s), "l"(g) : "memory");
}
__device__ __forceinline__ void cpa_commit() {
    asm volatile("cp.async.commit_group;" ::: "memory");
}
__device__ __forceinline__ float warp_sum(float v) {
#pragma unroll
    for (int o = 16; o; o >>= 1) v += __shfl_xor_sync(0xffffffffu, v, o);
    return v;
}
__device__ __forceinline__ float warp_max(float v) {
#pragma unroll
    for (int o = 16; o; o >>= 1) v = fmaxf(v, __shfl_xor_sync(0xffffffffu, v, o));
    return v;
}
__device__ __forceinline__ int winrow_to_token(int i) {
    int win = i / NTOK, n = i - win * NTOK;
    int b   = win >> 8;
    int wr  = win & 255;
    int wi  = wr >> 4, wj = wr & 15;
    int r   = n / WS,  c = n - r * WS;
    int hs  = wi * WS + r + SHIFT; if (hs >= HH)   hs  -= HH;
    int ws_ = wj * WS + c + SHIFT; if (ws_ >= WWID) ws_ -= WWID;
    return b * LTOK + hs * WWID + ws_;
}
__device__ __forceinline__ uint32_t pack2(float a, float b) {
    __nv_bfloat162 t = __floats2bfloat162_rn(a, b);
    return *reinterpret_cast<uint32_t*>(&t);
}
__device__ __forceinline__ void store_bf16x4(__nv_bfloat16* p, float a, float b, float c, float d) {
    uint2 u; u.x = pack2(a, b); u.y = pack2(c, d);
    *reinterpret_cast<uint2*>(p) = u;
}

// ---------------- fused prep: transpose + weight convert + bias table ----------------
#define W0 (CDIM*3*CDIM)
#define W1 (CDIM*CDIM)
#define W2 (CDIM*MLP)
#define W3 (MLP*CDIM)
#define WTOT (W0+W1+W2+W3)
#define SETUP_TOT (WTOT + HEADS*NTOK*NTOK)

__global__ __launch_bounds__(256) void k_prep(const float* __restrict__ x,
                                              const float* __restrict__ qkv_w,
                                              const float* __restrict__ proj_w,
                                              const float* __restrict__ fc1_w,
                                              const float* __restrict__ fc2_w,
                                              const float* __restrict__ tbl,
                                              const int* __restrict__ relidx) {
    int tid = threadIdx.x;
    if (blockIdx.y < BB) {
        // transpose (B,C,L) -> token-major g_xt
        __shared__ float t[CDIM*33];
        int b  = blockIdx.y;
        int l0 = blockIdx.x * 32;
        int lane = tid & 31, warp = tid >> 5;

        const float* xb = x + (size_t)b * CDIM * LTOK + l0;
        {
            int l = tid & 31, cg = tid >> 5;
#pragma unroll
            for (int it = 0; it < 16; it++) {
                int c = it * 8 + cg;
                t[c * 33 + l] = xb[(size_t)c * LTOK + l];
            }
        }
        __syncthreads();
#pragma unroll
        for (int kk = 0; kk < 4; kk++) {
            int tt = warp * 4 + kk;
            int l  = l0 + tt;
            float4 v;
            v.x = t[(lane*4+0)*33 + tt];
            v.y = t[(lane*4+1)*33 + tt];
            v.z = t[(lane*4+2)*33 + tt];
            v.w = t[(lane*4+3)*33 + tt];
            reinterpret_cast<float4*>(g_xt + (size_t)(b * LTOK + l) * CDIM)[lane] = v;
        }
    } else {
        // setup: weights -> bf16, rel-pos bias table
        int i = ((blockIdx.y - BB) * gridDim.x + blockIdx.x) * 256 + tid;
        if (i >= SETUP_TOT) return;
        if (i < W0)           { g_wqkv[i]          = __float2bfloat16(qkv_w[i]);          return; }
        if (i < W0+W1)        { g_wproj[i-W0]      = __float2bfloat16(proj_w[i-W0]);      return; }
        if (i < W0+W1+W2)     { g_wfc1[i-W0-W1]    = __float2bfloat16(fc1_w[i-W0-W1]);    return; }
        if (i < WTOT)         { g_wfc2[i-W0-W1-W2] = __float2bfloat16(fc2_w[i-W0-W1-W2]); return; }
        int j = i - WTOT;
        int h = j / (NTOK*NTOK);
        int e = j - h * (NTOK*NTOK);
        g_bias[h*NTOK*NTOK + e] = tbl[relidx[e]*HEADS + h];
    }
}

// ---------------- WMMA attention (R11-measured 82.9us, frozen) ----------------
__global__ __launch_bounds__(128, 8) void k_attn() {
    __shared__ __nv_bfloat16 sQ[64*40];   // Q, then V (O-phase)
    __shared__ __nv_bfloat16 sK[64*40];   // K, then patch scratch (O-phase)
    __shared__ float         sS[64*68];   // S fp32 -> P bf16 (in-place)

    int bid  = blockIdx.x;
    int win  = bid >> 2;
    int head = bid & 3;
    int tid  = threadIdx.x;
    int warp = tid >> 5, lane = tid & 31;

    const uint32_t sQ32 = smem_u32(sQ), sK32 = smem_u32(sK);
    const __nv_bfloat16* src = g_qkv + (size_t)win * NTOK * (3*CDIM) + head * HD;

#pragma unroll
    for (int it = 0; it < 4; it++) {
        int idx = it * 128 + tid;
        if (idx < 392) {
            int q = idx >> 2, part = idx & 3;
            int n = q >> 1, m = q & 1;
            cpa16((m ? sK32 : sQ32) + (uint32_t)(n*80 + part*16),
                  src + (size_t)n*(3*CDIM) + m*CDIM + part*8);
        }
    }
    cpa_commit();
    asm volatile("cp.async.wait_group 0;" ::: "memory");
    __syncthreads();

    {
        int wrow = warp * 16;
        wmma::fragment<wmma::accumulator,16,16,16,float> s[4];
#pragma unroll
        for (int j = 0; j < 4; j++) wmma::fill_fragment(s[j], 0.f);
#pragma unroll
        for (int i = 0; i < 2; i++) {
            wmma::fragment<wmma::matrix_a,16,16,16,__nv_bfloat16,wmma::row_major> qa;
            wmma::load_matrix_sync(qa, &sQ[wrow*40 + 16*i], 40);
#pragma unroll
            for (int j = 0; j < 4; j++) {
                wmma::fragment<wmma::matrix_b,16,16,16,__nv_bfloat16,wmma::col_major> kb;
                wmma::load_matrix_sync(kb, &sK[(16*j)*40 + 16*i], 40);
                wmma::mma_sync(s[j], qa, kb, s[j]);
            }
        }
#pragma unroll
        for (int j = 0; j < 4; j++)
            wmma::store_matrix_sync(&sS[wrow*68 + 16*j], s[j], 68, wmma::mem_row_major);
    }
    __syncthreads();

#pragma unroll
    for (int it = 0; it < 2; it++) {
        int idx = it * 128 + tid;
        if (idx < 196) {
            int n = idx >> 2, part = idx & 3;
            cpa16(sQ32 + (uint32_t)(n*80 + part*16),
                  src + (size_t)n*(3*CDIM) + 2*CDIM + part*8);
        }
    }
    cpa_commit();
    for (int i = tid; i < 300; i += 128) {
        int r = i / 20, c = i - r * 20;
        reinterpret_cast<uint32_t*>(sQ + (49 + r)*40)[c] = 0u;
    }

    {
        __nv_bfloat16* sP = reinterpret_cast<__nv_bfloat16*>(sS);
        const float scale = 0.17677669529663687f;
        for (int r = warp; r < NTOK; r += 4) {
            const float* brow = &g_bias[head*NTOK*NTOK + r*NTOK];
            int c2 = lane + 32;
            float v1 = sS[r*68 + lane] * scale + __ldg(&brow[lane]);
            float v2 = (c2 < NTOK) ? sS[r*68 + c2] * scale + __ldg(&brow[c2]) : -1e30f;
            float mx = warp_max(fmaxf(v1, v2));
            float e1 = __expf(v1 - mx);
            float e2 = (c2 < NTOK) ? __expf(v2 - mx) : 0.f;
            float rinv = 1.f / warp_sum(e1 + e2);
            sP[r*136 + lane] = __float2bfloat16(e1 * rinv);
            sP[r*136 + c2]   = __float2bfloat16(e2 * rinv);
        }
    }
    asm volatile("cp.async.wait_group 0;" ::: "memory");
    __syncthreads();

    {
        const __nv_bfloat16* sP = reinterpret_cast<const __nv_bfloat16*>(sS);
        const __nv_bfloat16* sV = sQ;
        int wrow = warp * 16;
        wmma::fragment<wmma::accumulator,16,16,16,float> o[2];
#pragma unroll
        for (int j = 0; j < 2; j++) wmma::fill_fragment(o[j], 0.f);
#pragma unroll
        for (int i = 0; i < 4; i++) {
            wmma::fragment<wmma::matrix_a,16,16,16,__nv_bfloat16,wmma::row_major> pa;
            wmma::load_matrix_sync(pa, &sP[wrow*136 + 16*i], 136);
#pragma unroll
            for (int j = 0; j < 2; j++) {
                wmma::fragment<wmma::matrix_b,16,16,16,__nv_bfloat16,wmma::row_major> vb;
                wmma::load_matrix_sync(vb, &sV[(16*i)*40 + 16*j], 40);
                wmma::mma_sync(o[j], pa, vb, o[j]);
            }
        }
        float* patch = reinterpret_cast<float*>(sK) + warp * 320;
        int r2 = lane >> 1;
        int cc = (lane & 1) * 8;
        int n  = wrow + r2;
#pragma unroll
        for (int j = 0; j < 2; j++) {
            wmma::store_matrix_sync(patch, o[j], 20, wmma::mem_row_major);
            __syncwarp();
            float4 v0 = *reinterpret_cast<float4*>(patch + r2*20 + cc);
            float4 v1 = *reinterpret_cast<float4*>(patch + r2*20 + cc + 4);
            __syncwarp();
            if (n < NTOK) {
                uint4 u;
                u.x = pack2(v0.x, v0.y); u.y = pack2(v0.z, v0.w);
                u.z = pack2(v1.x, v1.y); u.w = pack2(v1.z, v1.w);
                *reinterpret_cast<uint4*>(g_attnout + ((size_t)win * NTOK + n) * CDIM
                                          + head * HD + j*16 + cc) = u;
            }
        }
    }
}

// ---------------- cp.async double-buffered WMMA GEMM (qkv / fc1), R13 shape ---------
// EPI: 0 = QKV (LN1-fused A-load), 2 = FC1 (cp.async A, gelu)
#define TILEB   34816   // 128 x 136 bf16
#define TILEA64 17408   // 64 x 136 bf16
#define PATCHB  10240   // 8 warps x 320 floats

extern __shared__ __align__(16) unsigned char gdyn[];

template<int NT128, int EPI>
__device__ __forceinline__ void gemm_body(
    const __nv_bfloat16* __restrict__ A,       // unused for EPI==0
    const __nv_bfloat16* __restrict__ Bw,      // [K=128][N]
    const float* __restrict__ bias,
    const float* __restrict__ ln_g,
    const float* __restrict__ ln_b)
{
    const int N = NT128 * 128, K = 128;
    unsigned char* sAb = gdyn;
    unsigned char* sBb = gdyn + TILEB;
    const uint32_t sA32 = smem_u32(sAb), sB32 = smem_u32(sBb);

    const int tid = threadIdx.x;
    const int warp = tid >> 5, lane = tid & 31;
    const int bm = blockIdx.x * 128;
    const int wm = (warp & 3) * 32, wn = (warp >> 2) * 64;
    const int G = NT128;

    auto issue = [&](int g) {
        const __nv_bfloat16* src = Bw + g*128;
        uint32_t sb = sB32 + (uint32_t)(g & 1) * TILEB;
#pragma unroll
        for (int it = 0; it < 8; it++) {
            int idx = it * 256 + tid;
            int r = idx >> 4, c = idx & 15;
            cpa16(sb + r*272 + c*16, src + (size_t)r * N + c*8);
        }
        if (EPI == 2 && g == 0) {
            const __nv_bfloat16* sa = A + (size_t)bm * K;
#pragma unroll
            for (int it = 0; it < 8; it++) {
                int idx = it * 256 + tid;
                int r = idx >> 4, c = idx & 15;
                cpa16(sA32 + r*272 + c*16, sa + (size_t)r * K + c*8);
            }
        }
        cpa_commit();
    };

    issue(0);
    if (G > 1) issue(1);

    if (EPI == 0) {
        // LN1-fused A staging: gather window-order rows from g_xt, LN fp32, bf16 -> sA
        __nv_bfloat16* sA = reinterpret_cast<__nv_bfloat16*>(sAb);
        float4 gg = reinterpret_cast<const float4*>(ln_g)[lane];
        float4 bb = reinterpret_cast<const float4*>(ln_b)[lane];
#pragma unroll
        for (int r = warp; r < 128; r += 8) {
            int token = winrow_to_token(bm + r);
            float4 v = reinterpret_cast<const float4*>(g_xt + (size_t)token * CDIM)[lane];
            float s  = v.x + v.y + v.z + v.w;
            float s2 = v.x*v.x + v.y*v.y + v.z*v.z + v.w*v.w;
            s  = warp_sum(s); s2 = warp_sum(s2);
            float mean = s * (1.f / CDIM);
            float var  = s2 * (1.f / CDIM) - mean * mean;
            float inv  = rsqrtf(var + 1e-5f);
            store_bf16x4(sA + r*136 + lane*4,
                         (v.x - mean) * inv * gg.x + bb.x,
                         (v.y - mean) * inv * gg.y + bb.y,
                         (v.z - mean) * inv * gg.z + bb.z,
                         (v.w - mean) * inv * gg.w + bb.w);
        }
    }

    wmma::fragment<wmma::accumulator,16,16,16,float> acc[2][4];

#pragma unroll 1
    for (int g = 0; g < G; g++) {
        if (g + 1 < G) asm volatile("cp.async.wait_group 1;" ::: "memory");
        else           asm volatile("cp.async.wait_group 0;" ::: "memory");
        __syncthreads();

#pragma unroll
        for (int i = 0; i < 2; i++)
#pragma unroll
            for (int j = 0; j < 4; j++) wmma::fill_fragment(acc[i][j], 0.f);

        const __nv_bfloat16* pA = reinterpret_cast<const __nv_bfloat16*>(sAb);
        const __nv_bfloat16* pB = reinterpret_cast<const __nv_bfloat16*>(
            sBb + (size_t)(g & 1) * TILEB);
#pragma unroll
        for (int kk = 0; kk < 8; kk++) {
            wmma::fragment<wmma::matrix_a,16,16,16,__nv_bfloat16,wmma::row_major> af[2];
#pragma unroll
            for (int i = 0; i < 2; i++)
                wmma::load_matrix_sync(af[i], &pA[(wm + 16*i)*136 + kk*16], 136);
#pragma unroll
            for (int j = 0; j < 4; j++) {
                wmma::fragment<wmma::matrix_b,16,16,16,__nv_bfloat16,wmma::row_major> bf;
                wmma::load_matrix_sync(bf, &pB[(kk*16)*136 + wn + 16*j], 136);
#pragma unroll
                for (int i = 0; i < 2; i++)
                    wmma::mma_sync(acc[i][j], af[i], bf, acc[i][j]);
            }
        }
        __syncthreads();              // B buffer (g&1) consumed
        if (g + 2 < G) issue(g + 2);  // prefetch overlaps epilogue below

        // dedicated-patch epilogue (no block syncs; overlapped with prefetch)
        const int ncol = (EPI == 0) ? 3*CDIM : MLP;
        __nv_bfloat16* base = (EPI == 0) ? g_qkv : g_hh;
        float* patch = reinterpret_cast<float*>(gdyn + 3*TILEB) + warp * 320;
        int r2 = lane >> 1;
        int cc = (lane & 1) * 8;
#pragma unroll
        for (int i = 0; i < 2; i++) {
#pragma unroll
            for (int j = 0; j < 4; j++) {
                wmma::store_matrix_sync(patch, acc[i][j], 20, wmma::mem_row_major);
                __syncwarp();
                float4 v0 = *reinterpret_cast<float4*>(patch + r2*20 + cc);
                float4 v1 = *reinterpret_cast<float4*>(patch + r2*20 + cc + 4);
                __syncwarp();
                int gr = bm + wm + 16*i + r2;
                int gc = g*128 + wn + 16*j + cc;
                float4 b0 = __ldg(reinterpret_cast<const float4*>(bias + gc));
                float4 b1 = __ldg(reinterpret_cast<const float4*>(bias + gc + 4));
                v0.x += b0.x; v0.y += b0.y; v0.z += b0.z; v0.w += b0.w;
                v1.x += b1.x; v1.y += b1.y; v1.z += b1.z; v1.w += b1.w;
                if (EPI == 2) {
                    const float is2 = 0.70710678118654752f;
                    v0.x = 0.5f*v0.x*(1.f+erff(v0.x*is2));
                    v0.y = 0.5f*v0.y*(1.f+erff(v0.y*is2));
                    v0.z = 0.5f*v0.z*(1.f+erff(v0.z*is2));
                    v0.w = 0.5f*v0.w*(1.f+erff(v0.w*is2));
                    v1.x = 0.5f*v1.x*(1.f+erff(v1.x*is2));
                    v1.y = 0.5f*v1.y*(1.f+erff(v1.y*is2));
                    v1.z = 0.5f*v1.z*(1.f+erff(v1.z*is2));
                    v1.w = 0.5f*v1.w*(1.f+erff(v1.w*is2));
                }
                uint4 o;
                o.x = pack2(v0.x, v0.y); o.y = pack2(v0.z, v0.w);
                o.z = pack2(v1.x, v1.y); o.w = pack2(v1.z, v1.w);
                *reinterpret_cast<uint4*>(base + (size_t)gr * ncol + gc) = o;
            }
        }
    }
}

__global__ __launch_bounds__(256) void k_gemm_qkv(const float* bias, const float* g1, const float* b1) {
    gemm_body<3,0>(nullptr, g_wqkv, bias, g1, b1);
}
__global__ __launch_bounds__(256) void k_gemm_fc1(const float* bias) {
    gemm_body<4,2>(g_h, g_wfc1, bias, nullptr, nullptr);
}

// ---------------- proj: 16x128 warp tiles, reg/patch LN2 epilogue (R13, frozen) ----
__global__ __launch_bounds__(256) void k_gemm_proj(const float* __restrict__ bias,
                                                   const float* __restrict__ ln_g,
                                                   const float* __restrict__ ln_b) {
    unsigned char* sAb = gdyn;
    unsigned char* sBb = gdyn + TILEB;
    const uint32_t sA32 = smem_u32(sAb), sB32 = smem_u32(sBb);

    const int tid = threadIdx.x;
    const int warp = tid >> 5, lane = tid & 31;
    const int bm = blockIdx.x * 128;
    const int wm = warp * 16;

    {
        const __nv_bfloat16* sa = g_attnout + (size_t)bm * CDIM;
#pragma unroll
        for (int it = 0; it < 8; it++) {
            int idx = it * 256 + tid;
            int r = idx >> 4, c = idx & 15;
            cpa16(sA32 + r*272 + c*16, sa + (size_t)r * CDIM + c*8);
        }
#pragma unroll
        for (int it = 0; it < 8; it++) {
            int idx = it * 256 + tid;
            int r = idx >> 4, c = idx & 15;
            cpa16(sB32 + r*272 + c*16, g_wproj + (size_t)r * CDIM + c*8);
        }
        cpa_commit();
    }
    asm volatile("cp.async.wait_group 0;" ::: "memory");
    __syncthreads();

    wmma::fragment<wmma::accumulator,16,16,16,float> acc[8];
#pragma unroll
    for (int j = 0; j < 8; j++) wmma::fill_fragment(acc[j], 0.f);
    {
        const __nv_bfloat16* pA = reinterpret_cast<const __nv_bfloat16*>(sAb);
        const __nv_bfloat16* pB = reinterpret_cast<const __nv_bfloat16*>(sBb);
#pragma unroll
        for (int kk = 0; kk < 8; kk++) {
            wmma::fragment<wmma::matrix_a,16,16,16,__nv_bfloat16,wmma::row_major> af;
            wmma::load_matrix_sync(af, &pA[wm*136 + kk*16], 136);
#pragma unroll
            for (int j = 0; j < 8; j++) {
                wmma::fragment<wmma::matrix_b,16,16,16,__nv_bfloat16,wmma::row_major> bf;
                wmma::load_matrix_sync(bf, &pB[(kk*16)*136 + 16*j], 136);
                wmma::mma_sync(acc[j], af, bf, acc[j]);
            }
        }
    }
    __syncthreads();   // A/B fully consumed -> reuse as warp-private patches

    float* patch = reinterpret_cast<float*>(gdyn) + warp * 2112;
#pragma unroll
    for (int j = 0; j < 8; j++)
        wmma::store_matrix_sync(&patch[16*j], acc[j], 132, wmma::mem_row_major);
    __syncwarp();

    float4 pb = reinterpret_cast<const float4*>(bias)[lane];
    float4 gg = reinterpret_cast<const float4*>(ln_g)[lane];
    float4 lb = reinterpret_cast<const float4*>(ln_b)[lane];
#pragma unroll
    for (int r = 0; r < 16; r++) {
        int token = winrow_to_token(bm + wm + r);
        float4 v = *reinterpret_cast<float4*>(&patch[r*132 + lane*4]);
        float4 x = reinterpret_cast<const float4*>(g_xt + (size_t)token*CDIM)[lane];
        float4 y;
        y.x = v.x + pb.x + x.x;  y.y = v.y + pb.y + x.y;
        y.z = v.z + pb.z + x.z;  y.w = v.w + pb.w + x.w;
        reinterpret_cast<float4*>(g_y + (size_t)token*CDIM)[lane] = y;
        float s  = y.x + y.y + y.z + y.w;
        float s2 = y.x*y.x + y.y*y.y + y.z*y.z + y.w*y.w;
        s = warp_sum(s); s2 = warp_sum(s2);
        float mean = s * (1.f / CDIM);
        float var  = s2 * (1.f / CDIM) - mean * mean;
        float inv  = rsqrtf(var + 1e-5f);
        store_bf16x4(g_h + (size_t)token*CDIM + lane*4,
                     (y.x - mean) * inv * gg.x + lb.x,
                     (y.y - mean) * inv * gg.y + lb.y,
                     (y.z - mean) * inv * gg.z + lb.z,
                     (y.w - mean) * inv * gg.w + lb.w);
    }
}

// ---------------- fc2: 64-row M tiles, 2 CTA/SM, K=512 in 4 chunks (R12, frozen) ----
__global__ __launch_bounds__(256) void k_gemm_fc2(const float* __restrict__ bias,
                                                  float* __restrict__ outf) {
    unsigned char* sAb = gdyn;                    // 2 x 17408
    unsigned char* sBb = gdyn + 2*TILEA64;        // 2 x 34816
    const uint32_t sA32 = smem_u32(sAb), sB32 = smem_u32(sBb);

    const int tid = threadIdx.x;
    const int warp = tid >> 5, lane = tid & 31;
    const int bm = blockIdx.x * 64;
    const int wm = (warp & 1) * 32, wn = (warp >> 1) * 32;

    auto issue = [&](int g) {
        {
            const __nv_bfloat16* src = g_wfc2 + (size_t)(g*128) * CDIM;
            uint32_t sb = sB32 + (uint32_t)(g & 1) * TILEB;
#pragma unroll
            for (int it = 0; it < 8; it++) {
                int idx = it * 256 + tid;
                int r = idx >> 4, c = idx & 15;
                cpa16(sb + r*272 + c*16, src + (size_t)r * CDIM + c*8);
            }
        }
        {
            const __nv_bfloat16* src = g_hh + (size_t)bm * MLP + g*128;
            uint32_t sa = sA32 + (uint32_t)(g & 1) * TILEA64;
#pragma unroll
            for (int it = 0; it < 4; it++) {
                int idx = it * 256 + tid;
                int r = idx >> 4, c = idx & 15;
                cpa16(sa + r*272 + c*16, src + (size_t)r * MLP + c*8);
            }
        }
        cpa_commit();
    };

    issue(0);
    issue(1);

    wmma::fragment<wmma::accumulator,16,16,16,float> acc[2][2];
#pragma unroll
    for (int i = 0; i < 2; i++)
#pragma unroll
        for (int j = 0; j < 2; j++) wmma::fill_fragment(acc[i][j], 0.f);

#pragma unroll 1
    for (int g = 0; g < 4; g++) {
        if (g < 3) asm volatile("cp.async.wait_group 1;" ::: "memory");
        else       asm volatile("cp.async.wait_group 0;" ::: "memory");
        __syncthreads();

        const __nv_bfloat16* pA = reinterpret_cast<const __nv_bfloat16*>(
            sAb + (size_t)(g & 1) * TILEA64);
        const __nv_bfloat16* pB = reinterpret_cast<const __nv_bfloat16*>(
            sBb + (size_t)(g & 1) * TILEB);
#pragma unroll
        for (int kk = 0; kk < 8; kk++) {
            wmma::fragment<wmma::matrix_a,16,16,16,__nv_bfloat16,wmma::row_major> af[2];
#pragma unroll
            for (int i = 0; i < 2; i++)
                wmma::load_matrix_sync(af[i], &pA[(wm + 16*i)*136 + kk*16], 136);
#pragma unroll
            for (int j = 0; j < 2; j++) {
                wmma::fragment<wmma::matrix_b,16,16,16,__nv_bfloat16,wmma::row_major> bf;
                wmma::load_matrix_sync(bf, &pB[(kk*16)*136 + wn + 16*j], 136);
#pragma unroll
                for (int i = 0; i < 2; i++)
                    wmma::mma_sync(acc[i][j], af[i], bf, acc[i][j]);
            }
        }
        __syncthreads();
        if (g + 2 < 4) issue(g + 2);
    }

    float* sC = reinterpret_cast<float*>(sBb + TILEB);
#pragma unroll
    for (int i = 0; i < 2; i++)
#pragma unroll
        for (int j = 0; j < 2; j++)
            wmma::store_matrix_sync(&sC[(wm + 16*i)*132 + wn + 16*j],
                                    acc[i][j], 132, wmma::mem_row_major);
    __syncthreads();

    for (int e = tid; e < 64*128; e += 256) {
        int r = e >> 7, c = e & 127;
        sC[r*132 + c] += __ldg(&bias[c]) + g_y[(size_t)(bm + r)*CDIM + c];
    }
    __syncthreads();

    int b  = bm / LTOK;
    int l0 = bm - b * LTOK;
    float* ob = outf + (size_t)b * CDIM * LTOK + l0;
    int l = tid & 63, cb = tid >> 6;
#pragma unroll
    for (int it = 0; it < 32; it++) {
        int c = it * 4 + cb;
        ob[(size_t)c * LTOK + l] = sC[l*132 + c];
    }
}

// ---------------- launch ----------------
extern "C" void kernel_launch(void* const* d_in, const int* in_sizes, int n_in,
                              void* d_out, int out_size) {
    const float* x      = (const float*)d_in[0];
    const float* n1g    = (const float*)d_in[1];
    const float* n1b    = (const float*)d_in[2];
    const float* qkv_w  = (const float*)d_in[3];
    const float* qkv_b  = (const float*)d_in[4];
    const float* tbl    = (const float*)d_in[5];
    const int*   relidx = (const int*)d_in[6];
    const float* proj_w = (const float*)d_in[7];
    const float* proj_b = (const float*)d_in[8];
    const float* n2g    = (const float*)d_in[9];
    const float* n2b    = (const float*)d_in[10];
    const float* fc1_w  = (const float*)d_in[11];
    const float* fc1_b  = (const float*)d_in[12];
    const float* fc2_w  = (const float*)d_in[13];
    const float* fc2_b  = (const float*)d_in[14];
    float* out = (float*)d_out;

    const int GSM_QF  = 3 * TILEB + PATCHB;         // 114688: qkv/fc1 (A + 2B + patch)
    const int GSM_PRJ = 2 * TILEB;                  //  69632: proj (A + 1B)
    const int GSM_FC2 = 2 * TILEA64 + 2 * TILEB;    // 104448: fc2 (2A64 + 2B)

    cudaFuncSetAttribute(k_gemm_qkv,  cudaFuncAttributeMaxDynamicSharedMemorySize, GSM_QF);
    cudaFuncSetAttribute(k_gemm_fc1,  cudaFuncAttributeMaxDynamicSharedMemorySize, GSM_QF);
    cudaFuncSetAttribute(k_gemm_proj, cudaFuncAttributeMaxDynamicSharedMemorySize, GSM_PRJ);
    cudaFuncSetAttribute(k_gemm_fc2,  cudaFuncAttributeMaxDynamicSharedMemorySize, GSM_FC2);

    // merged transpose + setup: y in [0,BB) -> transpose; y in [BB,BB+3) -> setup
    k_prep<<<dim3(LTOK/32, BB + 3), 256>>>(x, qkv_w, proj_w, fc1_w, fc2_w, tbl, relidx);
    k_gemm_qkv<<<MTOK/128, 256, GSM_QF>>>(qkv_b, n1g, n1b);
    k_attn<<<NWIN*HEADS, 128>>>();
    k_gemm_proj<<<MTOK/128, 256, GSM_PRJ>>>(proj_b, n2g, n2b);
    k_gemm_fc1<<<MTOK/128, 256, GSM_QF>>>(fc1_b);
    k_gemm_fc2<<<MTOK/64, 256, GSM_FC2>>>(fc2_b, out);
}